// round 7
// baseline (speedup 1.0000x reference)
#include <cuda_runtime.h>
#include <cstdint>

#define TT  50
#define FF  24
#define H1  64
#define LAT 32
#define H3  64
#define BMAX 8192

typedef unsigned long long u64;

__device__ float g_h1[(size_t)BMAX * TT * H1];   // [B][T][64]
__device__ float g_z [(size_t)BMAX * LAT];

__device__ __forceinline__ float sigmoidf(float v) {
    return __fdividef(1.0f, 1.0f + __expf(-v));
}
__device__ __forceinline__ u64 ffma2(u64 a, u64 b, u64 c) {
    u64 d; asm("fma.rn.f32x2 %0, %1, %2, %3;" : "=l"(d) : "l"(a), "l"(b), "l"(c)); return d;
}
__device__ __forceinline__ u64 pack2(float lo, float hi) {
    u64 r; asm("mov.b64 %0, {%1, %2};" : "=l"(r) : "f"(lo), "f"(hi)); return r;
}
__device__ __forceinline__ float2 unpack2(u64 v) {
    float2 f; asm("mov.b64 {%0, %1}, %2;" : "=f"(f.x), "=f"(f.y) : "l"(v)); return f;
}

// ---------------------------------------------------------------------------
// LSTM1: x[B,T,24] -> g_h1[B,T,64]
// 128 threads, C=2 cols/thread, R=16 rows as two sequential groups of 8.
// ---------------------------------------------------------------------------
__global__ void __launch_bounds__(128, 2) lstm1_kernel(
    const float* __restrict__ x, const float* __restrict__ W,
    const float* __restrict__ U, const float* __restrict__ b, int B)
{
    constexpr int D = FF, H = H1, G = 4 * H1, R = 16;
    __shared__ __align__(16) float xs[2][R][D];
    __shared__ __align__(16) float hs[R][H];
    __shared__ __align__(16) float zs[R][G];

    const int j    = threadIdx.x;
    const int cA   = 2 * j, cB = 2 * j + 1;
    const int row0 = blockIdx.x * R;

    u64 wA[D / 2], wB[D / 2], uA[H / 2], uB[H / 2];
#pragma unroll
    for (int k = 0; k < D / 2; k++) {
        wA[k] = pack2(W[(2 * k) * G + cA], W[(2 * k + 1) * G + cA]);
        wB[k] = pack2(W[(2 * k) * G + cB], W[(2 * k + 1) * G + cB]);
    }
#pragma unroll
    for (int k = 0; k < H / 2; k++) {
        uA[k] = pack2(U[(2 * k) * G + cA], U[(2 * k + 1) * G + cA]);
        uB[k] = pack2(U[(2 * k) * G + cB], U[(2 * k + 1) * G + cB]);
    }
    const u64 bA = pack2(b[cA], 0.0f);
    const u64 bB = pack2(b[cB], 0.0f);

    for (int idx = j; idx < R * H; idx += 128) (&hs[0][0])[idx] = 0.0f;

    // gate tasks: 8 per thread. um=j&63, rows rb+2q (q=0..7).
    const int um = j & (H - 1);
    const int rb = j >> 6;             // 0..1
    float cst[8];
#pragma unroll
    for (int q = 0; q < 8; q++) cst[q] = 0.0f;

    // x staging: R*D = 384 elems; thread loads idx j, j+128, j+256
    const int lr0 = (j +   0) / D, lk0 = (j +   0) - lr0 * D;
    const int lr1 = (j + 128) / D, lk1 = (j + 128) - lr1 * D;
    const int lr2 = (j + 256) / D, lk2 = (j + 256) - lr2 * D;
    float xr0, xr1, xr2;
    {
        xr0 = x[((size_t)min(row0 + lr0, B - 1) * TT + 0) * D + lk0];
        xr1 = x[((size_t)min(row0 + lr1, B - 1) * TT + 0) * D + lk1];
        xr2 = x[((size_t)min(row0 + lr2, B - 1) * TT + 0) * D + lk2];
    }

    int buf = 0;
    for (int t = 0; t < TT; t++) {
        xs[buf][lr0][lk0] = xr0;
        xs[buf][lr1][lk1] = xr1;
        xs[buf][lr2][lk2] = xr2;
        if (t + 1 < TT) {
            xr0 = x[((size_t)min(row0 + lr0, B - 1) * TT + (t + 1)) * D + lk0];
            xr1 = x[((size_t)min(row0 + lr1, B - 1) * TT + (t + 1)) * D + lk1];
            xr2 = x[((size_t)min(row0 + lr2, B - 1) * TT + (t + 1)) * D + lk2];
        }
        __syncthreads();   // A: xs + hs(t-1) visible

#pragma unroll
        for (int g = 0; g < 2; g++) {
            const int rg = 8 * g;
            u64 aA[8], aB[8];
#pragma unroll
            for (int r = 0; r < 8; r++) { aA[r] = bA; aB[r] = bB; }
#pragma unroll
            for (int k = 0; k < D / 4; k++) {
#pragma unroll
                for (int r = 0; r < 8; r++) {
                    const ulonglong2 xv = *(const ulonglong2*)&xs[buf][rg + r][4 * k];
                    aA[r] = ffma2(xv.x, wA[2 * k], aA[r]);
                    aA[r] = ffma2(xv.y, wA[2 * k + 1], aA[r]);
                    aB[r] = ffma2(xv.x, wB[2 * k], aB[r]);
                    aB[r] = ffma2(xv.y, wB[2 * k + 1], aB[r]);
                }
            }
#pragma unroll
            for (int k = 0; k < H / 4; k++) {
#pragma unroll
                for (int r = 0; r < 8; r++) {
                    const ulonglong2 hv = *(const ulonglong2*)&hs[rg + r][4 * k];
                    aA[r] = ffma2(hv.x, uA[2 * k], aA[r]);
                    aA[r] = ffma2(hv.y, uA[2 * k + 1], aA[r]);
                    aB[r] = ffma2(hv.x, uB[2 * k], aB[r]);
                    aB[r] = ffma2(hv.y, uB[2 * k + 1], aB[r]);
                }
            }
#pragma unroll
            for (int r = 0; r < 8; r++) {
                const float2 pA = unpack2(aA[r]);
                const float2 pB = unpack2(aB[r]);
                *(float2*)&zs[rg + r][cA] = make_float2(pA.x + pA.y, pB.x + pB.y);
            }
        }
        __syncthreads();   // B: zs ready, hs reads done

#pragma unroll
        for (int q = 0; q < 8; q++) {
            const int r = rb + 2 * q;
            float zi = zs[r][um], zf = zs[r][H + um];
            float zg = zs[r][2 * H + um], zo = zs[r][3 * H + um];
            cst[q] = sigmoidf(zf) * cst[q] + sigmoidf(zi) * fmaxf(zg, 0.0f);
            float hn = sigmoidf(zo) * fmaxf(cst[q], 0.0f);
            hs[r][um] = hn;
            if (row0 + r < B) g_h1[((size_t)(row0 + r) * TT + t) * H + um] = hn;
        }
        buf ^= 1;
    }
}

// ---------------------------------------------------------------------------
// LSTM2: g_h1[B,T,64] -> g_z[B,32]. 64 threads, C=2, R=16 (two groups of 8).
// grid=512 @ 4 CTAs/SM -> single resident wave.
// ---------------------------------------------------------------------------
__global__ void __launch_bounds__(64, 4) lstm2_kernel(
    const float* __restrict__ W, const float* __restrict__ U,
    const float* __restrict__ b, int B)
{
    constexpr int D = H1, H = LAT, G = 4 * LAT, R = 16;
    __shared__ __align__(16) float xs[2][R][D];
    __shared__ __align__(16) float hs[R][H];
    __shared__ __align__(16) float zs[R][G];

    const int j    = threadIdx.x;
    const int cA   = 2 * j, cB = 2 * j + 1;
    const int row0 = blockIdx.x * R;

    u64 wA[D / 2], wB[D / 2], uA[H / 2], uB[H / 2];
#pragma unroll
    for (int k = 0; k < D / 2; k++) {
        wA[k] = pack2(W[(2 * k) * G + cA], W[(2 * k + 1) * G + cA]);
        wB[k] = pack2(W[(2 * k) * G + cB], W[(2 * k + 1) * G + cB]);
    }
#pragma unroll
    for (int k = 0; k < H / 2; k++) {
        uA[k] = pack2(U[(2 * k) * G + cA], U[(2 * k + 1) * G + cA]);
        uB[k] = pack2(U[(2 * k) * G + cB], U[(2 * k + 1) * G + cB]);
    }
    const u64 bA = pack2(b[cA], 0.0f);
    const u64 bB = pack2(b[cB], 0.0f);

    for (int idx = j; idx < R * H; idx += 64) (&hs[0][0])[idx] = 0.0f;

    const int um = j & (H - 1);
    const int rb = j >> 5;             // 0..1
    float cst[8];
#pragma unroll
    for (int q = 0; q < 8; q++) cst[q] = 0.0f;

    // staging: R*D = 1024 floats / 64 threads = 16 each (4x float4)
    const int lr = j >> 2, lk = (j & 3) * 16;
    float4 xg[4];
    {
        int row = min(row0 + lr, B - 1);
        const float4* p = (const float4*)&g_h1[((size_t)row * TT + 0) * D + lk];
#pragma unroll
        for (int i = 0; i < 4; i++) xg[i] = p[i];
    }

    int buf = 0;
    for (int t = 0; t < TT; t++) {
#pragma unroll
        for (int i = 0; i < 4; i++) *(float4*)&xs[buf][lr][lk + 4 * i] = xg[i];
        if (t + 1 < TT) {
            int row = min(row0 + lr, B - 1);
            const float4* p = (const float4*)&g_h1[((size_t)row * TT + (t + 1)) * D + lk];
#pragma unroll
            for (int i = 0; i < 4; i++) xg[i] = p[i];
        }
        __syncthreads();

#pragma unroll
        for (int g = 0; g < 2; g++) {
            const int rg = 8 * g;
            u64 aA[8], aB[8];
#pragma unroll
            for (int r = 0; r < 8; r++) { aA[r] = bA; aB[r] = bB; }
#pragma unroll
            for (int k = 0; k < D / 4; k++) {
#pragma unroll
                for (int r = 0; r < 8; r++) {
                    const ulonglong2 xv = *(const ulonglong2*)&xs[buf][rg + r][4 * k];
                    aA[r] = ffma2(xv.x, wA[2 * k], aA[r]);
                    aA[r] = ffma2(xv.y, wA[2 * k + 1], aA[r]);
                    aB[r] = ffma2(xv.x, wB[2 * k], aB[r]);
                    aB[r] = ffma2(xv.y, wB[2 * k + 1], aB[r]);
                }
            }
#pragma unroll
            for (int k = 0; k < H / 4; k++) {
#pragma unroll
                for (int r = 0; r < 8; r++) {
                    const ulonglong2 hv = *(const ulonglong2*)&hs[rg + r][4 * k];
                    aA[r] = ffma2(hv.x, uA[2 * k], aA[r]);
                    aA[r] = ffma2(hv.y, uA[2 * k + 1], aA[r]);
                    aB[r] = ffma2(hv.x, uB[2 * k], aB[r]);
                    aB[r] = ffma2(hv.y, uB[2 * k + 1], aB[r]);
                }
            }
#pragma unroll
            for (int r = 0; r < 8; r++) {
                const float2 pA = unpack2(aA[r]);
                const float2 pB = unpack2(aB[r]);
                *(float2*)&zs[rg + r][cA] = make_float2(pA.x + pA.y, pB.x + pB.y);
            }
        }
        __syncthreads();

#pragma unroll
        for (int q = 0; q < 8; q++) {
            const int r = rb + 2 * q;
            float zi = zs[r][um], zf = zs[r][H + um];
            float zg = zs[r][2 * H + um], zo = zs[r][3 * H + um];
            cst[q] = sigmoidf(zf) * cst[q] + sigmoidf(zi) * fmaxf(zg, 0.0f);
            float hn = sigmoidf(zo) * fmaxf(cst[q], 0.0f);
            hs[r][um] = hn;
            if (t == TT - 1 && row0 + r < B) g_z[(size_t)(row0 + r) * H + um] = hn;
        }
        buf ^= 1;
    }
}

// ---------------------------------------------------------------------------
// LSTM3 + Dense: g_z[B,32] -> out[B,T,24]. 128 threads, C=2, R=16.
// ---------------------------------------------------------------------------
__global__ void __launch_bounds__(128, 2) lstm3_kernel(
    const float* __restrict__ W, const float* __restrict__ U,
    const float* __restrict__ b, const float* __restrict__ Wd,
    const float* __restrict__ bd, float* __restrict__ out, int B)
{
    constexpr int D = LAT, H = H3, G = 4 * H3, R = 16;
    constexpr int WDP = 68;
    __shared__ __align__(16) float zin[R][D];
    __shared__ __align__(16) float hs[R][H];
    __shared__ __align__(16) float zb[R][G];
    __shared__ __align__(16) float wdst[FF][WDP];

    const int j    = threadIdx.x;
    const int cA   = 2 * j, cB = 2 * j + 1;
    const int row0 = blockIdx.x * R;

    u64 uA[H / 2], uB[H / 2];
#pragma unroll
    for (int k = 0; k < H / 2; k++) {
        uA[k] = pack2(U[(2 * k) * G + cA], U[(2 * k + 1) * G + cA]);
        uB[k] = pack2(U[(2 * k) * G + cB], U[(2 * k + 1) * G + cB]);
    }

    for (int idx = j; idx < H * FF; idx += 128) {
        int h = idx / FF, f = idx - h * FF;
        wdst[f][h] = Wd[idx];
    }
    for (int idx = j; idx < R * D; idx += 128) {
        int r = idx >> 5, k = idx & 31;
        int row = min(row0 + r, B - 1);
        zin[r][k] = g_z[(size_t)row * D + k];
    }
    for (int idx = j; idx < R * H; idx += 128) (&hs[0][0])[idx] = 0.0f;
    __syncthreads();

    // zw precompute (input constant over t)
    float zwA[R], zwB[R];
    {
        const float bvA = b[cA], bvB = b[cB];
#pragma unroll
        for (int r = 0; r < R; r++) { zwA[r] = bvA; zwB[r] = bvB; }
        for (int k = 0; k < D; k++) {
            const float wkA = W[k * G + cA], wkB = W[k * G + cB];
#pragma unroll
            for (int r = 0; r < R; r++) {
                zwA[r] += zin[r][k] * wkA;
                zwB[r] += zin[r][k] * wkB;
            }
        }
    }

    const int um = j & (H - 1);
    const int rb = j >> 6;             // 0..1
    float cst[8];
#pragma unroll
    for (int q = 0; q < 8; q++) cst[q] = 0.0f;

    // dense tasks: R*FF = 384 over 128 threads -> tasks j, j+128, j+256
    const int d0f = j % FF,           d0r = j / FF;
    const int d1f = (j + 128) % FF,   d1r = (j + 128) / FF;
    const int d2f = (j + 256) % FF,   d2r = (j + 256) / FF;
    const float bd0 = bd[d0f], bd1 = bd[d1f], bd2 = bd[d2f];

    for (int t = 0; t < TT; t++) {
#pragma unroll
        for (int g = 0; g < 2; g++) {
            const int rg = 8 * g;
            u64 aA[8], aB[8];
#pragma unroll
            for (int r = 0; r < 8; r++) {
                aA[r] = pack2(zwA[rg + r], 0.0f);
                aB[r] = pack2(zwB[rg + r], 0.0f);
            }
#pragma unroll
            for (int k = 0; k < H / 4; k++) {
#pragma unroll
                for (int r = 0; r < 8; r++) {
                    const ulonglong2 hv = *(const ulonglong2*)&hs[rg + r][4 * k];
                    aA[r] = ffma2(hv.x, uA[2 * k], aA[r]);
                    aA[r] = ffma2(hv.y, uA[2 * k + 1], aA[r]);
                    aB[r] = ffma2(hv.x, uB[2 * k], aB[r]);
                    aB[r] = ffma2(hv.y, uB[2 * k + 1], aB[r]);
                }
            }
#pragma unroll
            for (int r = 0; r < 8; r++) {
                const float2 pA = unpack2(aA[r]);
                const float2 pB = unpack2(aB[r]);
                *(float2*)&zb[rg + r][cA] = make_float2(pA.x + pA.y, pB.x + pB.y);
            }
        }
        __syncthreads();   // S2: zb ready, hs reads done

#pragma unroll
        for (int q = 0; q < 8; q++) {
            const int r = rb + 2 * q;
            float zi = zb[r][um], zf = zb[r][H + um];
            float zg = zb[r][2 * H + um], zo = zb[r][3 * H + um];
            cst[q] = sigmoidf(zf) * cst[q] + sigmoidf(zi) * fmaxf(zg, 0.0f);
            float hn = sigmoidf(zo) * fmaxf(cst[q], 0.0f);
            hs[r][um] = hn;
        }
        __syncthreads();   // S3: hs(t) visible

        // dense: 3 tasks/thread
        {
            int row = row0 + d0r;
            if (row < B) {
                u64 sacc = pack2(bd0, 0.0f);
#pragma unroll
                for (int k = 0; k < H / 4; k++) {
                    const ulonglong2 hv = *(const ulonglong2*)&hs[d0r][4 * k];
                    const ulonglong2 wv = *(const ulonglong2*)&wdst[d0f][4 * k];
                    sacc = ffma2(hv.x, wv.x, sacc);
                    sacc = ffma2(hv.y, wv.y, sacc);
                }
                const float2 p = unpack2(sacc);
                out[((size_t)row * TT + t) * FF + d0f] = p.x + p.y;
            }
        }
        {
            int row = row0 + d1r;
            if (row < B) {
                u64 sacc = pack2(bd1, 0.0f);
#pragma unroll
                for (int k = 0; k < H / 4; k++) {
                    const ulonglong2 hv = *(const ulonglong2*)&hs[d1r][4 * k];
                    const ulonglong2 wv = *(const ulonglong2*)&wdst[d1f][4 * k];
                    sacc = ffma2(hv.x, wv.x, sacc);
                    sacc = ffma2(hv.y, wv.y, sacc);
                }
                const float2 p = unpack2(sacc);
                out[((size_t)row * TT + t) * FF + d1f] = p.x + p.y;
            }
        }
        {
            int row = row0 + d2r;
            if (row < B) {
                u64 sacc = pack2(bd2, 0.0f);
#pragma unroll
                for (int k = 0; k < H / 4; k++) {
                    const ulonglong2 hv = *(const ulonglong2*)&hs[d2r][4 * k];
                    const ulonglong2 wv = *(const ulonglong2*)&wdst[d2f][4 * k];
                    sacc = ffma2(hv.x, wv.x, sacc);
                    sacc = ffma2(hv.y, wv.y, sacc);
                }
                const float2 p = unpack2(sacc);
                out[((size_t)row * TT + t) * FF + d2f] = p.x + p.y;
            }
        }
    }
}

// ---------------------------------------------------------------------------
extern "C" void kernel_launch(void* const* d_in, const int* in_sizes, int n_in,
                              void* d_out, int out_size)
{
    const float* x  = (const float*)d_in[0];
    const float* W1 = (const float*)d_in[1];
    const float* U1 = (const float*)d_in[2];
    const float* b1 = (const float*)d_in[3];
    const float* W2 = (const float*)d_in[4];
    const float* U2 = (const float*)d_in[5];
    const float* b2 = (const float*)d_in[6];
    const float* W3 = (const float*)d_in[7];
    const float* U3 = (const float*)d_in[8];
    const float* b3 = (const float*)d_in[9];
    const float* Wd = (const float*)d_in[10];
    const float* bd = (const float*)d_in[11];
    float* out = (float*)d_out;

    const int B = in_sizes[0] / (TT * FF);
    const int nblk = (B + 15) / 16;

    lstm1_kernel<<<nblk, 128>>>(x, W1, U1, b1, B);
    lstm2_kernel<<<nblk, 64>>>(W2, U2, b2, B);
    lstm3_kernel<<<nblk, 128>>>(W3, U3, b3, Wd, bd, out, B);
}